// round 1
// baseline (speedup 1.0000x reference)
#include <cuda_runtime.h>
#include <cuda_bf16.h>
#include <cstdint>

#define NN 10000
#define TT 24
#define NE 320000
#define HH 64
#define G4 256   // 4*H

// ---------------- scratch (static device globals; no allocs allowed) ----------------
__device__ float g_Hall[(size_t)TT * NN * HH];   // h * norm_src, per t
__device__ float g_Z[(size_t)TT * NN * HH];      // z0 * norm_src, per t
__device__ float g_P[(size_t)TT * NN];           // (z1*norm_src) . Wg2
__device__ int   g_deg_out[NN];
__device__ int   g_deg_in[NN];
__device__ int   g_cursor[NN];
__device__ int   g_offs[NN + 1];
__device__ int   g_csr[NE];                      // src indices grouped by dst
__device__ float g_nsrc[NN];
__device__ float g_ndst[NN];

// ---------------- helpers ----------------
__device__ __forceinline__ float sigf(float x) { return 1.0f / (1.0f + __expf(-x)); }
__device__ __forceinline__ float tanhf_(float x) { return 2.0f * sigf(2.0f * x) - 1.0f; }
__device__ __forceinline__ void bar64(int id) {
    asm volatile("bar.sync %0, 64;" :: "r"(id) : "memory");
}

// ---------------- setup kernels ----------------
__global__ void k_init() {
    int i = blockIdx.x * blockDim.x + threadIdx.x;
    if (i < NN) { g_deg_out[i] = 0; g_deg_in[i] = 0; g_cursor[i] = 0; }
}

__global__ void k_deg(const int* __restrict__ esrc, const int* __restrict__ edst) {
    int e = blockIdx.x * blockDim.x + threadIdx.x;
    if (e < NE) {
        atomicAdd(&g_deg_out[esrc[e]], 1);
        atomicAdd(&g_deg_in[edst[e]], 1);
    }
}

__global__ void k_norm() {
    int i = blockIdx.x * blockDim.x + threadIdx.x;
    if (i < NN) {
        int dout = g_deg_out[i], din = g_deg_in[i];
        g_nsrc[i] = (dout > 0) ? rsqrtf((float)dout) : 0.0f;
        g_ndst[i] = (din  > 0) ? rsqrtf((float)din)  : 0.0f;
    }
}

// single-block exclusive scan of g_deg_in -> g_offs (N+1)
__global__ void k_scan() {
    __shared__ int sh[1024];
    __shared__ int s_base;
    int tid = threadIdx.x;
    if (tid == 0) s_base = 0;
    __syncthreads();
    for (int chunk = 0; chunk * 1024 < NN; chunk++) {
        int i = chunk * 1024 + tid;
        int v = (i < NN) ? g_deg_in[i] : 0;
        sh[tid] = v;
        __syncthreads();
        for (int off = 1; off < 1024; off <<= 1) {
            int add = (tid >= off) ? sh[tid - off] : 0;
            __syncthreads();
            sh[tid] += add;
            __syncthreads();
        }
        int base = s_base;
        if (i < NN) g_offs[i + 1] = base + sh[tid];
        __syncthreads();
        if (tid == 1023) s_base = base + sh[1023];
        __syncthreads();
    }
    if (tid == 0) g_offs[0] = 0;
}

__global__ void k_scatter(const int* __restrict__ esrc, const int* __restrict__ edst) {
    int e = blockIdx.x * blockDim.x + threadIdx.x;
    if (e < NE) {
        int d = edst[e];
        int pos = g_offs[d] + atomicAdd(&g_cursor[d], 1);
        g_csr[pos] = esrc[e];
    }
}

// ---------------- phase 1: per-node LSTM, all T steps, W_hh loaded once ----------------
__global__ __launch_bounds__(256) void k_lstm(
    const float* __restrict__ blob,
    const float* __restrict__ Wih,
    const float* __restrict__ bih,
    const float* __restrict__ Whh,
    const float* __restrict__ bhh)
{
    int node = blockIdx.x;
    int g = threadIdx.x;       // gate-row 0..255

    __shared__ float h_sm[HH];
    __shared__ float gate_sm[G4];
    __shared__ float x_sm[TT];

    // load this thread's W_hh row into registers (64 floats)
    float w[HH];
    const float4* wp = (const float4*)(Whh + ((size_t)node * G4 + g) * HH);
#pragma unroll
    for (int i = 0; i < 16; i++) {
        float4 v = wp[i];
        w[4 * i + 0] = v.x; w[4 * i + 1] = v.y; w[4 * i + 2] = v.z; w[4 * i + 3] = v.w;
    }
    float wx   = Wih[(size_t)node * G4 + g];
    float bias = bih[(size_t)node * G4 + g] + bhh[(size_t)node * G4 + g];
    float ns   = g_nsrc[node];

    if (g < TT) x_sm[g] = blob[node * TT + g];
    if (g < HH) h_sm[g] = 0.0f;
    float c = 0.0f;
    __syncthreads();

    for (int t = 0; t < TT; t++) {
        float x = x_sm[t];
        float acc = fmaf(wx, x, bias);
#pragma unroll
        for (int k = 0; k < HH; k++)
            acc = fmaf(h_sm[k], w[k], acc);
        gate_sm[g] = acc;
        __syncthreads();
        if (g < HH) {
            float ig = gate_sm[g];
            float fg = gate_sm[g + 64];
            float gg = gate_sm[g + 128];
            float og = gate_sm[g + 192];
            c = sigf(fg) * c + sigf(ig) * tanhf_(gg);
            float hv = sigf(og) * tanhf_(c);
            h_sm[g] = hv;
            g_Hall[((size_t)t * NN + node) * HH + g] = hv * ns;
        }
        __syncthreads();
    }
}

// ---------------- phase 2: fused gconv (aggregate + 64x64 GEMM + relu + rescale) ----------------
// MODE 0: X=g_Hall -> Y=g_Z (stores z0*norm_src)
// MODE 1: X=g_Z    -> g_P   (stores (z1*norm_src).Wg2)
template<int MODE>
__global__ __launch_bounds__(256) void k_gconv(
    const float* __restrict__ W,     // (64,64) row-major
    const float* __restrict__ b,     // (64)
    const float* __restrict__ Wg2)   // (64) — only MODE 1
{
    __shared__ float Wsm[HH * HH];
    __shared__ float bsm[HH];
    __shared__ float w2sm[HH];
    __shared__ float agg[4][HH];
    __shared__ float pred[4][2];

    int tid = threadIdx.x;
    int grp = tid >> 6;          // 0..3
    int d   = tid & 63;
    int t   = blockIdx.y;

    for (int i = tid; i < HH * HH; i += 256) Wsm[i] = W[i];
    if (tid < HH) {
        bsm[tid] = b[tid];
        if (MODE == 1) w2sm[tid] = Wg2[tid];
    }
    __syncthreads();

    const float* __restrict__ X = (MODE == 0) ? g_Hall : g_Z;
    const float* Xt = X + (size_t)t * NN * HH;

    for (int it = 0; it < 4; it++) {
        int node = blockIdx.x * 16 + grp * 4 + it;
        bool valid = (node < NN);
        if (valid) {
            int rs = g_offs[node], re = g_offs[node + 1];
            float a0 = 0.f, a1 = 0.f, a2 = 0.f, a3 = 0.f;
            int e = rs;
            for (; e + 4 <= re; e += 4) {
                int s0 = g_csr[e + 0], s1 = g_csr[e + 1];
                int s2 = g_csr[e + 2], s3 = g_csr[e + 3];
                a0 += Xt[(size_t)s0 * HH + d];
                a1 += Xt[(size_t)s1 * HH + d];
                a2 += Xt[(size_t)s2 * HH + d];
                a3 += Xt[(size_t)s3 * HH + d];
            }
            for (; e < re; e++) a0 += Xt[(size_t)g_csr[e] * HH + d];
            agg[grp][d] = ((a0 + a1) + (a2 + a3)) * g_ndst[node];
        }
        bar64(grp + 1);
        if (valid) {
            float z = bsm[d];
#pragma unroll
            for (int k = 0; k < HH; k++)
                z = fmaf(agg[grp][k], Wsm[k * HH + d], z);
            z = fmaxf(z, 0.0f) * g_nsrc[node];
            if (MODE == 0) {
                g_Z[((size_t)t * NN + node) * HH + d] = z;
            } else {
                float partial = z * w2sm[d];
#pragma unroll
                for (int off = 16; off >= 1; off >>= 1)
                    partial += __shfl_xor_sync(0xffffffffu, partial, off);
                if ((d & 31) == 0) pred[grp][d >> 5] = partial;
            }
        }
        bar64(grp + 1);
        if (MODE == 1 && d == 0 && valid)
            g_P[(size_t)t * NN + node] = pred[grp][0] + pred[grp][1];
    }
}

// ---------------- final: scalar aggregation + output ----------------
__global__ void k_final(float* __restrict__ out, const float* __restrict__ bg2) {
    int idx = blockIdx.x * blockDim.x + threadIdx.x;
    if (idx >= NN * TT) return;
    int n = idx / TT;
    int t = idx % TT;
    int rs = g_offs[n], re = g_offs[n + 1];
    const float* Pt = g_P + (size_t)t * NN;
    float s0 = 0.f, s1 = 0.f, s2 = 0.f, s3 = 0.f;
    int e = rs;
    for (; e + 4 <= re; e += 4) {
        s0 += Pt[g_csr[e + 0]];
        s1 += Pt[g_csr[e + 1]];
        s2 += Pt[g_csr[e + 2]];
        s3 += Pt[g_csr[e + 3]];
    }
    for (; e < re; e++) s0 += Pt[g_csr[e]];
    float s = (s0 + s1) + (s2 + s3);
    out[idx] = g_ndst[n] * s + bg2[0];
}

// ---------------- launch ----------------
extern "C" void kernel_launch(void* const* d_in, const int* in_sizes, int n_in,
                              void* d_out, int out_size)
{
    const float* blob = (const float*)d_in[0];
    const float* Wih  = (const float*)d_in[1];
    const float* bih  = (const float*)d_in[2];
    const float* Whh  = (const float*)d_in[3];
    const float* bhh  = (const float*)d_in[4];
    const float* Wg0  = (const float*)d_in[5];
    const float* bg0  = (const float*)d_in[6];
    const float* Wg1  = (const float*)d_in[7];
    const float* bg1  = (const float*)d_in[8];
    const float* Wg2  = (const float*)d_in[9];
    const float* bg2  = (const float*)d_in[10];
    const int*   esrc = (const int*)d_in[11];
    const int*   edst = (const int*)d_in[12];
    float* out = (float*)d_out;

    k_init<<<(NN + 255) / 256, 256>>>();
    k_deg<<<(NE + 255) / 256, 256>>>(esrc, edst);
    k_norm<<<(NN + 255) / 256, 256>>>();
    k_scan<<<1, 1024>>>();
    k_scatter<<<(NE + 255) / 256, 256>>>(esrc, edst);

    k_lstm<<<NN, 256>>>(blob, Wih, bih, Whh, bhh);

    dim3 gg((NN + 15) / 16, TT);
    k_gconv<0><<<gg, 256>>>(Wg0, bg0, nullptr);
    k_gconv<1><<<gg, 256>>>(Wg1, bg1, Wg2);

    k_final<<<(NN * TT + 255) / 256, 256>>>(out, bg2);
}

// round 2
// speedup vs baseline: 1.3962x; 1.3962x over previous
#include <cuda_runtime.h>
#include <cuda_fp16.h>
#include <cstdint>

#define NN 10000
#define TT 24
#define NE 320000
#define HH 64
#define G4 256   // 4*H
#define FULL 0xffffffffu

// ---------------- scratch ----------------
__device__ __half2 g_Hh[(size_t)TT * NN * 32];   // h * norm_src, fp16, per t
__device__ __half2 g_Zh[(size_t)TT * NN * 32];   // z0 * norm_src, fp16, per t
__device__ float   g_P[(size_t)NN * TT + 32];    // (z1*norm_src) . Wg2, [node][t], padded
__device__ int     g_deg_out[NN];
__device__ int     g_deg_in[NN];
__device__ int     g_cursor[NN];
__device__ int     g_offs[NN + 1];
__device__ int     g_csr[NE];                    // src indices grouped by dst
__device__ float   g_nsrc[NN];
__device__ float   g_ndst[NN];

// ---------------- helpers ----------------
__device__ __forceinline__ float sigf(float x) { return 1.0f / (1.0f + __expf(-x)); }
__device__ __forceinline__ float tanhf_(float x) { return 2.0f * sigf(2.0f * x) - 1.0f; }

// ---------------- setup ----------------
__global__ void k_init() {
    int i = blockIdx.x * blockDim.x + threadIdx.x;
    if (i < NN) { g_deg_out[i] = 0; g_deg_in[i] = 0; g_cursor[i] = 0; }
}

__global__ void k_deg(const int* __restrict__ esrc, const int* __restrict__ edst) {
    int e = blockIdx.x * blockDim.x + threadIdx.x;
    if (e < NE) {
        atomicAdd(&g_deg_out[esrc[e]], 1);
        atomicAdd(&g_deg_in[edst[e]], 1);
    }
}

__global__ void k_norm() {
    int i = blockIdx.x * blockDim.x + threadIdx.x;
    if (i < NN) {
        int dout = g_deg_out[i], din = g_deg_in[i];
        g_nsrc[i] = (dout > 0) ? rsqrtf((float)dout) : 0.0f;
        g_ndst[i] = (din  > 0) ? rsqrtf((float)din)  : 0.0f;
    }
}

// single-block scan: 256 threads, 40 nodes/thread sequential + shuffle block scan
__global__ void k_scan() {
    __shared__ int warp_tot[8];
    int tid = threadIdx.x;
    const int PER = 40;
    int start = tid * PER;
    int sum = 0;
    for (int i = 0; i < PER; i++) {
        int n = start + i;
        if (n < NN) sum += g_deg_in[n];
    }
    int lane = tid & 31, w = tid >> 5;
    int inc = sum;
#pragma unroll
    for (int off = 1; off < 32; off <<= 1) {
        int v = __shfl_up_sync(FULL, inc, off);
        if (lane >= off) inc += v;
    }
    if (lane == 31) warp_tot[w] = inc;
    __syncthreads();
    if (w == 0) {
        int v = (lane < 8) ? warp_tot[lane] : 0;
#pragma unroll
        for (int off = 1; off < 8; off <<= 1) {
            int u = __shfl_up_sync(FULL, v, off);
            if (lane >= off) v += u;
        }
        if (lane < 8) warp_tot[lane] = v;
    }
    __syncthreads();
    int base = inc - sum + ((w > 0) ? warp_tot[w - 1] : 0);  // exclusive thread base
    int run = base;
    for (int i = 0; i < PER; i++) {
        int n = start + i;
        if (n < NN) { g_offs[n] = run; run += g_deg_in[n]; }
    }
    if (tid == 255) g_offs[NN] = base;   // threads past NN contribute 0 => base == total
}

__global__ void k_scatter(const int* __restrict__ esrc, const int* __restrict__ edst) {
    int e = blockIdx.x * blockDim.x + threadIdx.x;
    if (e < NE) {
        int d = edst[e];
        int pos = g_offs[d] + atomicAdd(&g_cursor[d], 1);
        g_csr[pos] = esrc[e];
    }
}

// ---------------- phase 1: per-node LSTM ----------------
__global__ __launch_bounds__(256) void k_lstm(
    const float* __restrict__ blob,
    const float* __restrict__ Wih,
    const float* __restrict__ bih,
    const float* __restrict__ Whh,
    const float* __restrict__ bhh)
{
    int node = blockIdx.x;
    int g = threadIdx.x;

    __shared__ __align__(16) float h_sm[HH];
    __shared__ float gate_sm[G4];
    __shared__ float x_sm[TT];

    float w[HH];
    const float4* wp = (const float4*)(Whh + ((size_t)node * G4 + g) * HH);
#pragma unroll
    for (int i = 0; i < 16; i++) {
        float4 v = wp[i];
        w[4 * i + 0] = v.x; w[4 * i + 1] = v.y; w[4 * i + 2] = v.z; w[4 * i + 3] = v.w;
    }
    float wx   = Wih[(size_t)node * G4 + g];
    float bias = bih[(size_t)node * G4 + g] + bhh[(size_t)node * G4 + g];
    float ns   = g_nsrc[node];

    if (g < TT) x_sm[g] = blob[node * TT + g];
    if (g < HH) h_sm[g] = 0.0f;
    float c = 0.0f;
    __syncthreads();

    __half* gH = (__half*)g_Hh;

    for (int t = 0; t < TT; t++) {
        float acc = fmaf(wx, x_sm[t], bias);
        const float4* h4 = (const float4*)h_sm;
#pragma unroll
        for (int k = 0; k < 16; k++) {
            float4 hv = h4[k];
            acc = fmaf(hv.x, w[4 * k + 0], acc);
            acc = fmaf(hv.y, w[4 * k + 1], acc);
            acc = fmaf(hv.z, w[4 * k + 2], acc);
            acc = fmaf(hv.w, w[4 * k + 3], acc);
        }
        gate_sm[g] = acc;
        __syncthreads();
        if (g < HH) {
            float ig = gate_sm[g];
            float fg = gate_sm[g + 64];
            float gg = gate_sm[g + 128];
            float og = gate_sm[g + 192];
            c = sigf(fg) * c + sigf(ig) * tanhf_(gg);
            float hv = sigf(og) * tanhf_(c);
            h_sm[g] = hv;
            gH[((size_t)t * NN + node) * HH + g] = __float2half_rn(hv * ns);
        }
        __syncthreads();
    }
}

// ---------------- phase 2: warp-per-node fused gconv ----------------
// MODE 0: gather g_Hh -> GEMM Wg0 -> relu -> *nsrc -> g_Zh (fp16)
// MODE 1: gather g_Zh -> GEMM Wg1 -> relu -> *nsrc -> dot Wg2 -> g_P[node][t]
template<int MODE>
__global__ __launch_bounds__(256) void k_gconv(
    const float* __restrict__ W,
    const float* __restrict__ b,
    const float* __restrict__ Wg2)
{
    __shared__ float Wsm[HH * HH];
    __shared__ float bsm[HH];
    __shared__ float w2sm[HH];
    __shared__ __align__(16) float aggsm[8][HH];

    int tid = threadIdx.x;
    int wp  = tid >> 5;
    int lane = tid & 31;
    int t = blockIdx.y;

    for (int i = tid; i < HH * HH; i += 256) Wsm[i] = W[i];
    if (tid < HH) {
        bsm[tid] = b[tid];
        if (MODE == 1) w2sm[tid] = Wg2[tid];
    }
    __syncthreads();

    int node = blockIdx.x * 8 + wp;
    if (node >= NN) return;

    const __half2* __restrict__ Xt =
        ((MODE == 0) ? g_Hh : g_Zh) + (size_t)t * NN * 32;

    int rs = g_offs[node], re = g_offs[node + 1];
    float ax0 = 0.f, ay0 = 0.f, ax1 = 0.f, ay1 = 0.f;

    for (int base = rs; base < re; base += 32) {
        int nloc = min(32, re - base);
        int idx = (lane < nloc) ? g_csr[base + lane] : 0;
        int j = 0;
        for (; j + 4 <= nloc; j += 4) {
            int s0 = __shfl_sync(FULL, idx, j + 0);
            int s1 = __shfl_sync(FULL, idx, j + 1);
            int s2 = __shfl_sync(FULL, idx, j + 2);
            int s3 = __shfl_sync(FULL, idx, j + 3);
            float2 v0 = __half22float2(Xt[(size_t)s0 * 32 + lane]);
            float2 v1 = __half22float2(Xt[(size_t)s1 * 32 + lane]);
            float2 v2 = __half22float2(Xt[(size_t)s2 * 32 + lane]);
            float2 v3 = __half22float2(Xt[(size_t)s3 * 32 + lane]);
            ax0 += v0.x + v1.x; ay0 += v0.y + v1.y;
            ax1 += v2.x + v3.x; ay1 += v2.y + v3.y;
        }
        for (; j < nloc; j++) {
            int s = __shfl_sync(FULL, idx, j);
            float2 v = __half22float2(Xt[(size_t)s * 32 + lane]);
            ax0 += v.x; ay0 += v.y;
        }
    }

    float nd = g_ndst[node];
    aggsm[wp][2 * lane + 0] = (ax0 + ax1) * nd;
    aggsm[wp][2 * lane + 1] = (ay0 + ay1) * nd;
    __syncwarp();

    int d0 = 2 * lane;
    float z0 = bsm[d0], z1 = bsm[d0 + 1];
    const float4* a4 = (const float4*)aggsm[wp];
#pragma unroll
    for (int k4 = 0; k4 < 16; k4++) {
        float4 a = a4[k4];
        int kb = k4 * 4;
        float2 w0 = ((const float2*)(Wsm + (kb + 0) * HH))[lane];
        float2 w1 = ((const float2*)(Wsm + (kb + 1) * HH))[lane];
        float2 w2 = ((const float2*)(Wsm + (kb + 2) * HH))[lane];
        float2 w3 = ((const float2*)(Wsm + (kb + 3) * HH))[lane];
        z0 = fmaf(a.x, w0.x, z0); z1 = fmaf(a.x, w0.y, z1);
        z0 = fmaf(a.y, w1.x, z0); z1 = fmaf(a.y, w1.y, z1);
        z0 = fmaf(a.z, w2.x, z0); z1 = fmaf(a.z, w2.y, z1);
        z0 = fmaf(a.w, w3.x, z0); z1 = fmaf(a.w, w3.y, z1);
    }

    float ns = g_nsrc[node];
    z0 = fmaxf(z0, 0.0f) * ns;
    z1 = fmaxf(z1, 0.0f) * ns;

    if (MODE == 0) {
        g_Zh[((size_t)t * NN + node) * 32 + lane] = __floats2half2_rn(z0, z1);
    } else {
        float p = z0 * w2sm[d0] + z1 * w2sm[d0 + 1];
#pragma unroll
        for (int off = 16; off >= 1; off >>= 1)
            p += __shfl_xor_sync(FULL, p, off);
        if (lane == 0) g_P[(size_t)node * TT + t] = p;
    }
}

// ---------------- final: warp-per-node, lane = t ----------------
__global__ __launch_bounds__(256) void k_final(float* __restrict__ out,
                                               const float* __restrict__ bg2) {
    int node = blockIdx.x * 8 + (threadIdx.x >> 5);
    int lane = threadIdx.x & 31;
    if (node >= NN) return;

    int rs = g_offs[node], re = g_offs[node + 1];
    float s0 = 0.f, s1 = 0.f, s2 = 0.f, s3 = 0.f;

    for (int base = rs; base < re; base += 32) {
        int nloc = min(32, re - base);
        int idx = (lane < nloc) ? g_csr[base + lane] : 0;
        int j = 0;
        for (; j + 4 <= nloc; j += 4) {
            int a0 = __shfl_sync(FULL, idx, j + 0);
            int a1 = __shfl_sync(FULL, idx, j + 1);
            int a2 = __shfl_sync(FULL, idx, j + 2);
            int a3 = __shfl_sync(FULL, idx, j + 3);
            s0 += g_P[(size_t)a0 * TT + lane];
            s1 += g_P[(size_t)a1 * TT + lane];
            s2 += g_P[(size_t)a2 * TT + lane];
            s3 += g_P[(size_t)a3 * TT + lane];
        }
        for (; j < nloc; j++) {
            int a = __shfl_sync(FULL, idx, j);
            s0 += g_P[(size_t)a * TT + lane];
        }
    }
    float s = (s0 + s1) + (s2 + s3);
    if (lane < TT)
        out[node * TT + lane] = g_ndst[node] * s + bg2[0];
}

// ---------------- launch ----------------
extern "C" void kernel_launch(void* const* d_in, const int* in_sizes, int n_in,
                              void* d_out, int out_size)
{
    const float* blob = (const float*)d_in[0];
    const float* Wih  = (const float*)d_in[1];
    const float* bih  = (const float*)d_in[2];
    const float* Whh  = (const float*)d_in[3];
    const float* bhh  = (const float*)d_in[4];
    const float* Wg0  = (const float*)d_in[5];
    const float* bg0  = (const float*)d_in[6];
    const float* Wg1  = (const float*)d_in[7];
    const float* bg1  = (const float*)d_in[8];
    const float* Wg2  = (const float*)d_in[9];
    const float* bg2  = (const float*)d_in[10];
    const int*   esrc = (const int*)d_in[11];
    const int*   edst = (const int*)d_in[12];
    float* out = (float*)d_out;

    k_init<<<(NN + 255) / 256, 256>>>();
    k_deg<<<(NE + 255) / 256, 256>>>(esrc, edst);
    k_norm<<<(NN + 255) / 256, 256>>>();
    k_scan<<<1, 256>>>();
    k_scatter<<<(NE + 255) / 256, 256>>>(esrc, edst);

    k_lstm<<<NN, 256>>>(blob, Wih, bih, Whh, bhh);

    dim3 gg((NN + 7) / 8, TT);
    k_gconv<0><<<gg, 256>>>(Wg0, bg0, nullptr);
    k_gconv<1><<<gg, 256>>>(Wg1, bg1, Wg2);

    k_final<<<(NN + 7) / 8, 256>>>(out, bg2);
}

// round 3
// speedup vs baseline: 1.4656x; 1.0497x over previous
#include <cuda_runtime.h>
#include <cuda_fp16.h>
#include <cstdint>

#define NN 10000
#define TT 24
#define NE 320000
#define HH 64
#define G4 256   // 4*H
#define FULL 0xffffffffu

// ---------------- scratch ----------------
__device__ __half2 g_Hh[(size_t)TT * NN * 32];   // h * norm_src, fp16, per t
__device__ __half2 g_Zh[(size_t)TT * NN * 32];   // z0 * norm_src, fp16, per t
__device__ float   g_P[(size_t)NN * TT + 32];    // (z1*norm_src) . Wg2, [node][t], padded
__device__ int     g_deg_out[NN];
__device__ int     g_deg_in[NN];
__device__ int     g_cursor[NN];
__device__ int     g_offs[NN + 1];
__device__ int     g_csr[NE];                    // src indices grouped by dst
__device__ float   g_nsrc[NN];
__device__ float   g_ndst[NN];

// ---------------- helpers ----------------
__device__ __forceinline__ float sigf(float x) { return 1.0f / (1.0f + __expf(-x)); }
__device__ __forceinline__ float tanhf_(float x) { return 2.0f * sigf(2.0f * x) - 1.0f; }

__device__ __forceinline__ unsigned long long packf2(float lo, float hi) {
    unsigned long long r;
    asm("mov.b64 %0, {%1, %2};" : "=l"(r) : "f"(lo), "f"(hi));
    return r;
}
__device__ __forceinline__ void unpackf2(unsigned long long v, float& lo, float& hi) {
    asm("mov.b64 {%0, %1}, %2;" : "=f"(lo), "=f"(hi) : "l"(v));
}
__device__ __forceinline__ void fma2(unsigned long long& d, unsigned long long a,
                                     unsigned long long b) {
    asm("fma.rn.f32x2 %0, %1, %2, %0;" : "+l"(d) : "l"(a), "l"(b));
}

// ---------------- setup ----------------
__global__ void k_init() {
    int i = blockIdx.x * blockDim.x + threadIdx.x;
    if (i < NN) { g_deg_out[i] = 0; g_deg_in[i] = 0; g_cursor[i] = 0; }
}

__global__ void k_deg(const int* __restrict__ esrc, const int* __restrict__ edst) {
    int e = blockIdx.x * blockDim.x + threadIdx.x;
    if (e < NE) {
        atomicAdd(&g_deg_out[esrc[e]], 1);
        atomicAdd(&g_deg_in[edst[e]], 1);
    }
}

__global__ void k_norm() {
    int i = blockIdx.x * blockDim.x + threadIdx.x;
    if (i < NN) {
        int dout = g_deg_out[i], din = g_deg_in[i];
        g_nsrc[i] = (dout > 0) ? rsqrtf((float)dout) : 0.0f;
        g_ndst[i] = (din  > 0) ? rsqrtf((float)din)  : 0.0f;
    }
}

// ---------------- phase 1: per-node LSTM (launched early for ncu slot) ----------------
__global__ __launch_bounds__(256) void k_lstm(
    const float* __restrict__ blob,
    const float* __restrict__ Wih,
    const float* __restrict__ bih,
    const float* __restrict__ Whh,
    const float* __restrict__ bhh)
{
    int node = blockIdx.x;
    int g = threadIdx.x;

    __shared__ __align__(16) float h_sm[HH];
    __shared__ float gate_sm[G4];
    __shared__ float x_sm[TT];

    // W_hh row as 32 packed f32x2
    unsigned long long w[32];
    const ulonglong2* wp = (const ulonglong2*)(Whh + ((size_t)node * G4 + g) * HH);
#pragma unroll
    for (int i = 0; i < 16; i++) {
        ulonglong2 v = wp[i];
        w[2 * i + 0] = v.x;
        w[2 * i + 1] = v.y;
    }
    float wx   = Wih[(size_t)node * G4 + g];
    float bias = bih[(size_t)node * G4 + g] + bhh[(size_t)node * G4 + g];
    float ns   = g_nsrc[node];

    if (g < TT) x_sm[g] = blob[node * TT + g];
    if (g < HH) h_sm[g] = 0.0f;
    float c = 0.0f;
    __syncthreads();

    __half* gH = (__half*)g_Hh;

    for (int t = 0; t < TT; t++) {
        unsigned long long acc0 = packf2(fmaf(wx, x_sm[t], bias), 0.0f);
        unsigned long long acc1 = packf2(0.0f, 0.0f);
        const ulonglong2* h2 = (const ulonglong2*)h_sm;
#pragma unroll
        for (int k = 0; k < 16; k++) {
            ulonglong2 hv = h2[k];
            fma2(acc0, hv.x, w[2 * k + 0]);
            fma2(acc1, hv.y, w[2 * k + 1]);
        }
        float a0, a1, a2, a3;
        unpackf2(acc0, a0, a1);
        unpackf2(acc1, a2, a3);
        gate_sm[g] = (a0 + a1) + (a2 + a3);
        __syncthreads();
        if (g < HH) {
            float ig = gate_sm[g];
            float fg = gate_sm[g + 64];
            float gg = gate_sm[g + 128];
            float og = gate_sm[g + 192];
            c = sigf(fg) * c + sigf(ig) * tanhf_(gg);
            float hv = sigf(og) * tanhf_(c);
            h_sm[g] = hv;
            gH[((size_t)t * NN + node) * HH + g] = __float2half_rn(hv * ns);
        }
        __syncthreads();
    }
}

// ---------------- scan: 1024 threads, 10 nodes/thread ----------------
__global__ void k_scan() {
    __shared__ int warp_tot[32];
    int tid = threadIdx.x;
    const int PER = 10;
    int start = tid * PER;
    int sum = 0;
#pragma unroll
    for (int i = 0; i < PER; i++) {
        int n = start + i;
        if (n < NN) sum += g_deg_in[n];
    }
    int lane = tid & 31, w = tid >> 5;
    int inc = sum;
#pragma unroll
    for (int off = 1; off < 32; off <<= 1) {
        int v = __shfl_up_sync(FULL, inc, off);
        if (lane >= off) inc += v;
    }
    if (lane == 31) warp_tot[w] = inc;
    __syncthreads();
    if (w == 0) {
        int v = warp_tot[lane];
#pragma unroll
        for (int off = 1; off < 32; off <<= 1) {
            int u = __shfl_up_sync(FULL, v, off);
            if (lane >= off) v += u;
        }
        warp_tot[lane] = v;
    }
    __syncthreads();
    int base = inc - sum + ((w > 0) ? warp_tot[w - 1] : 0);
    int run = base;
    for (int i = 0; i < PER; i++) {
        int n = start + i;
        if (n < NN) { g_offs[n] = run; run += g_deg_in[n]; }
    }
    if (tid == 1023) g_offs[NN] = base;   // tail threads past NN have sum 0
}

__global__ void k_scatter(const int* __restrict__ esrc, const int* __restrict__ edst) {
    int e = blockIdx.x * blockDim.x + threadIdx.x;
    if (e < NE) {
        int d = edst[e];
        int pos = g_offs[d] + atomicAdd(&g_cursor[d], 1);
        g_csr[pos] = esrc[e];
    }
}

// ---------------- phase 2: warp handles 4 nodes; fused gconv ----------------
// MODE 0: gather g_Hh -> GEMM Wg0 -> relu -> *nsrc -> g_Zh (fp16)
// MODE 1: gather g_Zh -> GEMM Wg1 -> relu -> *nsrc -> dot Wg2 -> g_P[node][t]
template<int MODE>
__global__ __launch_bounds__(256) void k_gconv(
    const float* __restrict__ W,
    const float* __restrict__ b,
    const float* __restrict__ Wg2)
{
    __shared__ float Wsm[HH * HH];
    __shared__ float bsm[HH];
    __shared__ float w2sm[HH];
    __shared__ __align__(16) float aggsm[8][HH];

    int tid = threadIdx.x;
    int wp  = tid >> 5;
    int lane = tid & 31;
    int t = blockIdx.y;

    for (int i = tid; i < HH * HH; i += 256) Wsm[i] = W[i];
    if (tid < HH) {
        bsm[tid] = b[tid];
        if (MODE == 1) w2sm[tid] = Wg2[tid];
    }
    __syncthreads();

    const __half2* __restrict__ Xt =
        ((MODE == 0) ? g_Hh : g_Zh) + (size_t)t * NN * 32;

    for (int it = 0; it < 4; it++) {
        int node = blockIdx.x * 32 + wp * 4 + it;
        if (node < NN) {
            int rs = g_offs[node], re = g_offs[node + 1];
            float ax0 = 0.f, ay0 = 0.f, ax1 = 0.f, ay1 = 0.f;

            for (int base = rs; base < re; base += 32) {
                int nloc = min(32, re - base);
                int idx = (lane < nloc) ? g_csr[base + lane] : 0;
                int j = 0;
                for (; j + 4 <= nloc; j += 4) {
                    int s0 = __shfl_sync(FULL, idx, j + 0);
                    int s1 = __shfl_sync(FULL, idx, j + 1);
                    int s2 = __shfl_sync(FULL, idx, j + 2);
                    int s3 = __shfl_sync(FULL, idx, j + 3);
                    float2 v0 = __half22float2(Xt[(size_t)s0 * 32 + lane]);
                    float2 v1 = __half22float2(Xt[(size_t)s1 * 32 + lane]);
                    float2 v2 = __half22float2(Xt[(size_t)s2 * 32 + lane]);
                    float2 v3 = __half22float2(Xt[(size_t)s3 * 32 + lane]);
                    ax0 += v0.x + v1.x; ay0 += v0.y + v1.y;
                    ax1 += v2.x + v3.x; ay1 += v2.y + v3.y;
                }
                for (; j < nloc; j++) {
                    int s = __shfl_sync(FULL, idx, j);
                    float2 v = __half22float2(Xt[(size_t)s * 32 + lane]);
                    ax0 += v.x; ay0 += v.y;
                }
            }

            float nd = g_ndst[node];
            aggsm[wp][2 * lane + 0] = (ax0 + ax1) * nd;
            aggsm[wp][2 * lane + 1] = (ay0 + ay1) * nd;
        }
        __syncwarp();
        if (node < NN) {
            int d0 = 2 * lane;
            float z0 = bsm[d0], z1 = bsm[d0 + 1];
            const float4* a4 = (const float4*)aggsm[wp];
#pragma unroll
            for (int k4 = 0; k4 < 16; k4++) {
                float4 a = a4[k4];
                int kb = k4 * 4;
                float2 w0 = ((const float2*)(Wsm + (kb + 0) * HH))[lane];
                float2 w1 = ((const float2*)(Wsm + (kb + 1) * HH))[lane];
                float2 w2 = ((const float2*)(Wsm + (kb + 2) * HH))[lane];
                float2 w3 = ((const float2*)(Wsm + (kb + 3) * HH))[lane];
                z0 = fmaf(a.x, w0.x, z0); z1 = fmaf(a.x, w0.y, z1);
                z0 = fmaf(a.y, w1.x, z0); z1 = fmaf(a.y, w1.y, z1);
                z0 = fmaf(a.z, w2.x, z0); z1 = fmaf(a.z, w2.y, z1);
                z0 = fmaf(a.w, w3.x, z0); z1 = fmaf(a.w, w3.y, z1);
            }

            float ns = g_nsrc[node];
            z0 = fmaxf(z0, 0.0f) * ns;
            z1 = fmaxf(z1, 0.0f) * ns;

            if (MODE == 0) {
                g_Zh[((size_t)t * NN + node) * 32 + lane] = __floats2half2_rn(z0, z1);
            } else {
                float p = z0 * w2sm[d0] + z1 * w2sm[d0 + 1];
#pragma unroll
                for (int off = 16; off >= 1; off >>= 1)
                    p += __shfl_xor_sync(FULL, p, off);
                if (lane == 0) g_P[(size_t)node * TT + t] = p;
            }
        }
        __syncwarp();
    }
}

// ---------------- final: warp-per-node, lane = t ----------------
__global__ __launch_bounds__(256) void k_final(float* __restrict__ out,
                                               const float* __restrict__ bg2) {
    int node = blockIdx.x * 8 + (threadIdx.x >> 5);
    int lane = threadIdx.x & 31;
    if (node >= NN) return;

    int rs = g_offs[node], re = g_offs[node + 1];
    float s0 = 0.f, s1 = 0.f, s2 = 0.f, s3 = 0.f;

    for (int base = rs; base < re; base += 32) {
        int nloc = min(32, re - base);
        int idx = (lane < nloc) ? g_csr[base + lane] : 0;
        int j = 0;
        for (; j + 4 <= nloc; j += 4) {
            int a0 = __shfl_sync(FULL, idx, j + 0);
            int a1 = __shfl_sync(FULL, idx, j + 1);
            int a2 = __shfl_sync(FULL, idx, j + 2);
            int a3 = __shfl_sync(FULL, idx, j + 3);
            s0 += g_P[(size_t)a0 * TT + lane];
            s1 += g_P[(size_t)a1 * TT + lane];
            s2 += g_P[(size_t)a2 * TT + lane];
            s3 += g_P[(size_t)a3 * TT + lane];
        }
        for (; j < nloc; j++) {
            int a = __shfl_sync(FULL, idx, j);
            s0 += g_P[(size_t)a * TT + lane];
        }
    }
    float s = (s0 + s1) + (s2 + s3);
    if (lane < TT)
        out[node * TT + lane] = g_ndst[node] * s + bg2[0];
}

// ---------------- launch ----------------
extern "C" void kernel_launch(void* const* d_in, const int* in_sizes, int n_in,
                              void* d_out, int out_size)
{
    const float* blob = (const float*)d_in[0];
    const float* Wih  = (const float*)d_in[1];
    const float* bih  = (const float*)d_in[2];
    const float* Whh  = (const float*)d_in[3];
    const float* bhh  = (const float*)d_in[4];
    const float* Wg0  = (const float*)d_in[5];
    const float* bg0  = (const float*)d_in[6];
    const float* Wg1  = (const float*)d_in[7];
    const float* bg1  = (const float*)d_in[8];
    const float* Wg2  = (const float*)d_in[9];
    const float* bg2  = (const float*)d_in[10];
    const int*   esrc = (const int*)d_in[11];
    const int*   edst = (const int*)d_in[12];
    float* out = (float*)d_out;

    k_init<<<(NN + 255) / 256, 256>>>();
    k_deg<<<(NE + 255) / 256, 256>>>(esrc, edst);
    k_norm<<<(NN + 255) / 256, 256>>>();

    // LSTM moved up (only needs g_nsrc) — lands in ncu's capture slot
    k_lstm<<<NN, 256>>>(blob, Wih, bih, Whh, bhh);

    k_scan<<<1, 1024>>>();
    k_scatter<<<(NE + 255) / 256, 256>>>(esrc, edst);

    dim3 gg((NN + 31) / 32, TT);
    k_gconv<0><<<gg, 256>>>(Wg0, bg0, nullptr);
    k_gconv<1><<<gg, 256>>>(Wg1, bg1, Wg2);

    k_final<<<(NN + 7) / 8, 256>>>(out, bg2);
}

// round 4
// speedup vs baseline: 1.4681x; 1.0017x over previous
#include <cuda_runtime.h>
#include <cuda_fp16.h>
#include <cstdint>

#define NN 10000
#define TT 24
#define NE 320000
#define HH 64
#define G4 256   // 4*H
#define FULL 0xffffffffu

// ---------------- scratch ----------------
__device__ __half2 g_Hh[(size_t)TT * NN * 32];   // h * norm_src, fp16, per t
__device__ __half2 g_Zh[(size_t)TT * NN * 32];   // z0 * norm_src, fp16, per t
__device__ float   g_P[(size_t)NN * TT + 32];    // (z1*norm_src) . Wg2, [node][t], padded
__device__ int     g_deg_out[NN];
__device__ int     g_deg_in[NN];
__device__ int     g_cursor[NN];
__device__ int     g_offs[NN + 1];
__device__ int     g_csr[NE];                    // src indices grouped by dst
__device__ float   g_nsrc[NN];
__device__ float   g_ndst[NN];

// ---------------- helpers ----------------
__device__ __forceinline__ float sigf(float x) { return 1.0f / (1.0f + __expf(-x)); }
__device__ __forceinline__ float tanhf_(float x) { return 2.0f * sigf(2.0f * x) - 1.0f; }

__device__ __forceinline__ unsigned long long packf2(float lo, float hi) {
    unsigned long long r;
    asm("mov.b64 %0, {%1, %2};" : "=l"(r) : "f"(lo), "f"(hi));
    return r;
}
__device__ __forceinline__ void unpackf2(unsigned long long v, float& lo, float& hi) {
    asm("mov.b64 {%0, %1}, %2;" : "=f"(lo), "=f"(hi) : "l"(v));
}
__device__ __forceinline__ void fma2(unsigned long long& d, unsigned long long a,
                                     unsigned long long b) {
    asm("fma.rn.f32x2 %0, %1, %2, %0;" : "+l"(d) : "l"(a), "l"(b));
}

// ---------------- setup ----------------
__global__ void k_init() {
    int i = blockIdx.x * blockDim.x + threadIdx.x;
    if (i < NN) { g_deg_out[i] = 0; g_deg_in[i] = 0; g_cursor[i] = 0; }
}

__global__ void k_deg(const int* __restrict__ esrc, const int* __restrict__ edst) {
    int e = blockIdx.x * blockDim.x + threadIdx.x;
    if (e < NE) {
        atomicAdd(&g_deg_out[esrc[e]], 1);
        atomicAdd(&g_deg_in[edst[e]], 1);
    }
}

__global__ void k_norm() {
    int i = blockIdx.x * blockDim.x + threadIdx.x;
    if (i < NN) {
        int dout = g_deg_out[i], din = g_deg_in[i];
        g_nsrc[i] = (dout > 0) ? rsqrtf((float)dout) : 0.0f;
        g_ndst[i] = (din  > 0) ? rsqrtf((float)din)  : 0.0f;
    }
}

// ---------------- phase 1: per-node LSTM (launched early for ncu slot) ----------------
__global__ __launch_bounds__(256) void k_lstm(
    const float* __restrict__ blob,
    const float* __restrict__ Wih,
    const float* __restrict__ bih,
    const float* __restrict__ Whh,
    const float* __restrict__ bhh)
{
    int node = blockIdx.x;
    int g = threadIdx.x;

    __shared__ __align__(16) float h_sm[HH];
    __shared__ float gate_sm[G4];
    __shared__ float x_sm[TT];

    // W_hh row as 32 packed f32x2
    unsigned long long w[32];
    const ulonglong2* wp = (const ulonglong2*)(Whh + ((size_t)node * G4 + g) * HH);
#pragma unroll
    for (int i = 0; i < 16; i++) {
        ulonglong2 v = wp[i];
        w[2 * i + 0] = v.x;
        w[2 * i + 1] = v.y;
    }
    float wx   = Wih[(size_t)node * G4 + g];
    float bias = bih[(size_t)node * G4 + g] + bhh[(size_t)node * G4 + g];
    float ns   = g_nsrc[node];

    if (g < TT) x_sm[g] = blob[node * TT + g];
    if (g < HH) h_sm[g] = 0.0f;
    float c = 0.0f;
    __syncthreads();

    __half* gH = (__half*)g_Hh;

    for (int t = 0; t < TT; t++) {
        unsigned long long acc0 = packf2(fmaf(wx, x_sm[t], bias), 0.0f);
        unsigned long long acc1 = packf2(0.0f, 0.0f);
        const ulonglong2* h2 = (const ulonglong2*)h_sm;
#pragma unroll
        for (int k = 0; k < 16; k++) {
            ulonglong2 hv = h2[k];
            fma2(acc0, hv.x, w[2 * k + 0]);
            fma2(acc1, hv.y, w[2 * k + 1]);
        }
        float a0, a1, a2, a3;
        unpackf2(acc0, a0, a1);
        unpackf2(acc1, a2, a3);
        gate_sm[g] = (a0 + a1) + (a2 + a3);
        __syncthreads();
        if (g < HH) {
            float ig = gate_sm[g];
            float fg = gate_sm[g + 64];
            float gg = gate_sm[g + 128];
            float og = gate_sm[g + 192];
            c = sigf(fg) * c + sigf(ig) * tanhf_(gg);
            float hv = sigf(og) * tanhf_(c);
            h_sm[g] = hv;
            gH[((size_t)t * NN + node) * HH + g] = __float2half_rn(hv * ns);
        }
        __syncthreads();
    }
}

// ---------------- scan: 1024 threads, 10 nodes/thread ----------------
__global__ void k_scan() {
    __shared__ int warp_tot[32];
    int tid = threadIdx.x;
    const int PER = 10;
    int start = tid * PER;
    int sum = 0;
#pragma unroll
    for (int i = 0; i < PER; i++) {
        int n = start + i;
        if (n < NN) sum += g_deg_in[n];
    }
    int lane = tid & 31, w = tid >> 5;
    int inc = sum;
#pragma unroll
    for (int off = 1; off < 32; off <<= 1) {
        int v = __shfl_up_sync(FULL, inc, off);
        if (lane >= off) inc += v;
    }
    if (lane == 31) warp_tot[w] = inc;
    __syncthreads();
    if (w == 0) {
        int v = warp_tot[lane];
#pragma unroll
        for (int off = 1; off < 32; off <<= 1) {
            int u = __shfl_up_sync(FULL, v, off);
            if (lane >= off) v += u;
        }
        warp_tot[lane] = v;
    }
    __syncthreads();
    int base = inc - sum + ((w > 0) ? warp_tot[w - 1] : 0);
    int run = base;
    for (int i = 0; i < PER; i++) {
        int n = start + i;
        if (n < NN) { g_offs[n] = run; run += g_deg_in[n]; }
    }
    if (tid == 1023) g_offs[NN] = base;   // tail threads past NN have sum 0
}

__global__ void k_scatter(const int* __restrict__ esrc, const int* __restrict__ edst) {
    int e = blockIdx.x * blockDim.x + threadIdx.x;
    if (e < NE) {
        int d = edst[e];
        int pos = g_offs[d] + atomicAdd(&g_cursor[d], 1);
        g_csr[pos] = esrc[e];
    }
}

// ---------------- phase 2: warp handles 4 nodes; fused gconv ----------------
// MODE 0: gather g_Hh -> GEMM Wg0 -> relu -> *nsrc -> g_Zh (fp16)
// MODE 1: gather g_Zh -> GEMM Wg1 -> relu -> *nsrc -> dot Wg2 -> g_P[node][t]
template<int MODE>
__global__ __launch_bounds__(256) void k_gconv(
    const float* __restrict__ W,
    const float* __restrict__ b,
    const float* __restrict__ Wg2)
{
    __shared__ float Wsm[HH * HH];
    __shared__ float bsm[HH];
    __shared__ float w2sm[HH];
    __shared__ __align__(16) float aggsm[8][HH];

    int tid = threadIdx.x;
    int wp  = tid >> 5;
    int lane = tid & 31;
    int t = blockIdx.y;

    for (int i = tid; i < HH * HH; i += 256) Wsm[i] = W[i];
    if (tid < HH) {
        bsm[tid] = b[tid];
        if (MODE == 1) w2sm[tid] = Wg2[tid];
    }
    __syncthreads();

    const __half2* __restrict__ Xt =
        ((MODE == 0) ? g_Hh : g_Zh) + (size_t)t * NN * 32;

    for (int it = 0; it < 4; it++) {
        int node = blockIdx.x * 32 + wp * 4 + it;
        if (node < NN) {
            int rs = g_offs[node], re = g_offs[node + 1];
            float ax0 = 0.f, ay0 = 0.f, ax1 = 0.f, ay1 = 0.f;

            for (int base = rs; base < re; base += 32) {
                int nloc = min(32, re - base);
                int idx = (lane < nloc) ? g_csr[base + lane] : 0;
                int j = 0;
                for (; j + 4 <= nloc; j += 4) {
                    int s0 = __shfl_sync(FULL, idx, j + 0);
                    int s1 = __shfl_sync(FULL, idx, j + 1);
                    int s2 = __shfl_sync(FULL, idx, j + 2);
                    int s3 = __shfl_sync(FULL, idx, j + 3);
                    float2 v0 = __half22float2(Xt[(size_t)s0 * 32 + lane]);
                    float2 v1 = __half22float2(Xt[(size_t)s1 * 32 + lane]);
                    float2 v2 = __half22float2(Xt[(size_t)s2 * 32 + lane]);
                    float2 v3 = __half22float2(Xt[(size_t)s3 * 32 + lane]);
                    ax0 += v0.x + v1.x; ay0 += v0.y + v1.y;
                    ax1 += v2.x + v3.x; ay1 += v2.y + v3.y;
                }
                for (; j < nloc; j++) {
                    int s = __shfl_sync(FULL, idx, j);
                    float2 v = __half22float2(Xt[(size_t)s * 32 + lane]);
                    ax0 += v.x; ay0 += v.y;
                }
            }

            float nd = g_ndst[node];
            aggsm[wp][2 * lane + 0] = (ax0 + ax1) * nd;
            aggsm[wp][2 * lane + 1] = (ay0 + ay1) * nd;
        }
        __syncwarp();
        if (node < NN) {
            int d0 = 2 * lane;
            float z0 = bsm[d0], z1 = bsm[d0 + 1];
            const float4* a4 = (const float4*)aggsm[wp];
#pragma unroll
            for (int k4 = 0; k4 < 16; k4++) {
                float4 a = a4[k4];
                int kb = k4 * 4;
                float2 w0 = ((const float2*)(Wsm + (kb + 0) * HH))[lane];
                float2 w1 = ((const float2*)(Wsm + (kb + 1) * HH))[lane];
                float2 w2 = ((const float2*)(Wsm + (kb + 2) * HH))[lane];
                float2 w3 = ((const float2*)(Wsm + (kb + 3) * HH))[lane];
                z0 = fmaf(a.x, w0.x, z0); z1 = fmaf(a.x, w0.y, z1);
                z0 = fmaf(a.y, w1.x, z0); z1 = fmaf(a.y, w1.y, z1);
                z0 = fmaf(a.z, w2.x, z0); z1 = fmaf(a.z, w2.y, z1);
                z0 = fmaf(a.w, w3.x, z0); z1 = fmaf(a.w, w3.y, z1);
            }

            float ns = g_nsrc[node];
            z0 = fmaxf(z0, 0.0f) * ns;
            z1 = fmaxf(z1, 0.0f) * ns;

            if (MODE == 0) {
                g_Zh[((size_t)t * NN + node) * 32 + lane] = __floats2half2_rn(z0, z1);
            } else {
                float p = z0 * w2sm[d0] + z1 * w2sm[d0 + 1];
#pragma unroll
                for (int off = 16; off >= 1; off >>= 1)
                    p += __shfl_xor_sync(FULL, p, off);
                if (lane == 0) g_P[(size_t)node * TT + t] = p;
            }
        }
        __syncwarp();
    }
}

// ---------------- final: warp-per-node, lane = t ----------------
__global__ __launch_bounds__(256) void k_final(float* __restrict__ out,
                                               const float* __restrict__ bg2) {
    int node = blockIdx.x * 8 + (threadIdx.x >> 5);
    int lane = threadIdx.x & 31;
    if (node >= NN) return;

    int rs = g_offs[node], re = g_offs[node + 1];
    float s0 = 0.f, s1 = 0.f, s2 = 0.f, s3 = 0.f;

    for (int base = rs; base < re; base += 32) {
        int nloc = min(32, re - base);
        int idx = (lane < nloc) ? g_csr[base + lane] : 0;
        int j = 0;
        for (; j + 4 <= nloc; j += 4) {
            int a0 = __shfl_sync(FULL, idx, j + 0);
            int a1 = __shfl_sync(FULL, idx, j + 1);
            int a2 = __shfl_sync(FULL, idx, j + 2);
            int a3 = __shfl_sync(FULL, idx, j + 3);
            s0 += g_P[(size_t)a0 * TT + lane];
            s1 += g_P[(size_t)a1 * TT + lane];
            s2 += g_P[(size_t)a2 * TT + lane];
            s3 += g_P[(size_t)a3 * TT + lane];
        }
        for (; j < nloc; j++) {
            int a = __shfl_sync(FULL, idx, j);
            s0 += g_P[(size_t)a * TT + lane];
        }
    }
    float s = (s0 + s1) + (s2 + s3);
    if (lane < TT)
        out[node * TT + lane] = g_ndst[node] * s + bg2[0];
}

// ---------------- launch ----------------
extern "C" void kernel_launch(void* const* d_in, const int* in_sizes, int n_in,
                              void* d_out, int out_size)
{
    const float* blob = (const float*)d_in[0];
    const float* Wih  = (const float*)d_in[1];
    const float* bih  = (const float*)d_in[2];
    const float* Whh  = (const float*)d_in[3];
    const float* bhh  = (const float*)d_in[4];
    const float* Wg0  = (const float*)d_in[5];
    const float* bg0  = (const float*)d_in[6];
    const float* Wg1  = (const float*)d_in[7];
    const float* bg1  = (const float*)d_in[8];
    const float* Wg2  = (const float*)d_in[9];
    const float* bg2  = (const float*)d_in[10];
    const int*   esrc = (const int*)d_in[11];
    const int*   edst = (const int*)d_in[12];
    float* out = (float*)d_out;

    k_init<<<(NN + 255) / 256, 256>>>();
    k_deg<<<(NE + 255) / 256, 256>>>(esrc, edst);
    k_norm<<<(NN + 255) / 256, 256>>>();

    // LSTM moved up (only needs g_nsrc) — lands in ncu's capture slot
    k_lstm<<<NN, 256>>>(blob, Wih, bih, Whh, bhh);

    k_scan<<<1, 1024>>>();
    k_scatter<<<(NE + 255) / 256, 256>>>(esrc, edst);

    dim3 gg((NN + 31) / 32, TT);
    k_gconv<0><<<gg, 256>>>(Wg0, bg0, nullptr);
    k_gconv<1><<<gg, 256>>>(Wg1, bg1, Wg2);

    k_final<<<(NN + 7) / 8, 256>>>(out, bg2);
}